// round 5
// baseline (speedup 1.0000x reference)
#include <cuda_runtime.h>
#include <cuda_bf16.h>

#define NBINS 10
#define WARPS_PER_BLOCK 8

// Global scratch (no device allocation allowed). Zero-initialized at module
// load; last block resets after finalize; atomicInc wrap resets g_done.
__device__ float g_sums[NBINS];
__device__ float g_cnts[NBINS];
__device__ unsigned int g_done;

__global__ __launch_bounds__(256, 8) void ghmc_fused(
    const float4* __restrict__ pred4,
    const int4*   __restrict__ targ4,
    const float4* __restrict__ lw4,
    int n4,
    float* __restrict__ out)
{
    // Per-warp privatized packed histogram:
    //   bits [0,40)  : sum of round(bce * 2^20)  (fixed point)
    //   bits [40,64) : count of valid elements
    __shared__ unsigned long long sh_hist[WARPS_PER_BLOCK][NBINS];

    const int tid  = threadIdx.x;
    const int wid  = tid >> 5;

    if (tid < WARPS_PER_BLOCK * NBINS)
        ((unsigned long long*)sh_hist)[tid] = 0ULL;
    __syncthreads();

    unsigned long long* myrow = sh_hist[wid];

    const int stride = gridDim.x * blockDim.x;
    for (int i = blockIdx.x * blockDim.x + tid; i < n4; i += stride) {
        float4 p = pred4[i];
        int4   t = targ4[i];
        float4 w = lw4[i];

        float px[4] = {p.x, p.y, p.z, p.w};
        int   tx[4] = {t.x, t.y, t.z, t.w};
        float wx[4] = {w.x, w.y, w.z, w.w};

#pragma unroll
        for (int k = 0; k < 4; k++) {
            float x  = px[k];
            int   ti = tx[k];
            bool  valid = wx[k] > 0.0f;

            // e = exp(-|x|) via exp2 (fabs/neg fold into operand modifiers)
            float e = exp2f(-1.44269504f * fabsf(x));
            float r = __fdividef(1.0f, 1.0f + e);   // sigmoid(|x|)

            // g = |sigmoid(x) - t| = sigmoid(x*(1-2t))
            float xp = (ti != 0) ? -x : x;
            float g  = (xp >= 0.0f) ? r : e * r;

            int bin = min((int)(g * 10.0f), NBINS - 1);

            // bce = max(x,0) - x*t + log1p(e);  log(1+e) = -ln2*log2(r)
            float bce = fmaf(-x, (float)ti, fmaxf(x, 0.0f));
            bce = fmaf(-0.69314718f, __log2f(r), bce);

            if (valid) {
                // bce >= 0, <= ~7 -> fits easily in 23 bits at 2^20 scale
                unsigned int fx = (unsigned int)__float2int_rn(bce * 1048576.0f);
                unsigned long long addend = (1ULL << 40) | (unsigned long long)fx;
                atomicAdd(&myrow[bin], addend);
            }
        }
    }
    __syncthreads();

    // Fold 8 warp rows per bin (u64 adds: sum<2^39, cnt<2^17 -> no carry),
    // unpack, push to global float accumulators.
    if (tid < NBINS) {
        unsigned long long acc = 0ULL;
#pragma unroll
        for (int w = 0; w < WARPS_PER_BLOCK; w++)
            acc += sh_hist[w][tid];
        float sum = (float)(acc & ((1ULL << 40) - 1ULL)) * (1.0f / 1048576.0f);
        float cnt = (float)(acc >> 40);
        atomicAdd(&g_sums[tid], sum);
        atomicAdd(&g_cnts[tid], cnt);
    }

    // --- last-block finalize (threadfence reduction pattern) ---
    __shared__ bool is_last;
    if (tid == 0) {
        __threadfence();
        unsigned r = atomicInc(&g_done, gridDim.x - 1);  // wraps to 0 on last
        is_last = (r == gridDim.x - 1);
    }
    __syncthreads();

    if (is_last && tid < 32) {
        __threadfence();
        float contrib = 0.0f;
        float nb = 0.0f;
        if (tid < NBINS) {
            float cb = __ldcg(&g_cnts[tid]);
            float sb = __ldcg(&g_sums[tid]);
            contrib = sb / fmaxf(cb, 1.0f);   // empty bin: sb==0 -> 0
            nb = (cb > 0.0f) ? 1.0f : 0.0f;
            g_cnts[tid] = 0.0f;               // reset for next graph replay
            g_sums[tid] = 0.0f;
        }
#pragma unroll
        for (int o = 16; o > 0; o >>= 1) {
            contrib += __shfl_down_sync(0xffffffffu, contrib, o);
            nb      += __shfl_down_sync(0xffffffffu, nb, o);
        }
        if (tid == 0)
            out[0] = contrib / fmaxf(nb, 1.0f);   // LOSS_WEIGHT = 1.0
    }
}

extern "C" void kernel_launch(void* const* d_in, const int* in_sizes, int n_in,
                              void* d_out, int out_size) {
    const float4* pred4 = (const float4*)d_in[0];
    const int4*   targ4 = (const int4*)d_in[1];
    const float4* lw4   = (const float4*)d_in[2];
    float* out = (float*)d_out;

    int n  = in_sizes[0];
    int n4 = n >> 2;   // 67,108,864 / 4 = 16,777,216

    // 148 SMs x 8 resident blocks -> exactly one full wave at <=32 regs.
    ghmc_fused<<<1184, 256>>>(pred4, targ4, lw4, n4, out);
}

// round 6
// speedup vs baseline: 2.5469x; 2.5469x over previous
#include <cuda_runtime.h>
#include <cuda_bf16.h>

#define NBINS 10
#define TPB 256

// Global scratch (no device allocation allowed). Zero-initialized at module
// load; last block resets after finalize; atomicInc wrap resets g_done.
__device__ float g_sums[NBINS];
__device__ float g_cnts[NBINS];
__device__ unsigned int g_done;

__global__ __launch_bounds__(TPB, 8) void ghmc_fused(
    const float4* __restrict__ pred4,
    const int4*   __restrict__ targ4,
    const float4* __restrict__ lw4,
    int n4,
    float* __restrict__ out)
{
    // Per-THREAD private histogram slots: hist[bin][tid] = (sum, count).
    // [bin][tid] layout -> lane l always hits banks 2l,2l+1: conflict-free.
    __shared__ float2 hist[NBINS][TPB];   // 20 KB

    const int tid = threadIdx.x;

#pragma unroll
    for (int b = 0; b < NBINS; b++)
        hist[b][tid] = make_float2(0.0f, 0.0f);
    // No sync needed: slots are thread-private until the fold.

    const int stride = gridDim.x * blockDim.x;
    for (int i = blockIdx.x * blockDim.x + tid; i < n4; i += stride) {
        float4 p = pred4[i];
        int4   t = targ4[i];
        float4 w = lw4[i];

        float px[4] = {p.x, p.y, p.z, p.w};
        int   tx[4] = {t.x, t.y, t.z, t.w};
        float wx[4] = {w.x, w.y, w.z, w.w};

#pragma unroll
        for (int k = 0; k < 4; k++) {
            float x  = px[k];
            int   ti = tx[k];
            bool  valid = wx[k] > 0.0f;

            // e = exp(-|x|) via exp2 (fabs/neg fold into operand modifiers)
            float e = exp2f(-1.44269504f * fabsf(x));
            float r = __fdividef(1.0f, 1.0f + e);   // sigmoid(|x|)

            // g = |sigmoid(x) - t| = sigmoid(x*(1-2t))
            float xp = (ti != 0) ? -x : x;
            float g  = (xp >= 0.0f) ? r : e * r;

            int bin = min((int)(g * 10.0f), NBINS - 1);

            // bce = max(x,0) - x*t + log1p(e);  log(1+e) = -ln2*log2(r)
            float bce = fmaf(-x, (float)ti, fmaxf(x, 0.0f));
            bce = fmaf(-0.69314718f, __log2f(r), bce);

            float v  = valid ? bce  : 0.0f;   // invalid adds (0,0): branchless
            float cf = valid ? 1.0f : 0.0f;

            float2 acc = hist[bin][tid];      // LDS.64
            acc.x += v;
            acc.y += cf;
            hist[bin][tid] = acc;             // STS.64
        }
    }
    __syncthreads();

    // In-smem tree fold over the 256 thread columns (counts stay f32-exact).
#pragma unroll
    for (int off = TPB / 2; off > 0; off >>= 1) {
        if (tid < off) {
#pragma unroll
            for (int b = 0; b < NBINS; b++) {
                float2 a = hist[b][tid];
                float2 o = hist[b][tid + off];
                hist[b][tid] = make_float2(a.x + o.x, a.y + o.y);
            }
        }
        __syncthreads();
    }

    if (tid < NBINS) {
        atomicAdd(&g_sums[tid], hist[tid][0].x);
        atomicAdd(&g_cnts[tid], hist[tid][0].y);
    }

    // --- last-block finalize (threadfence reduction pattern) ---
    __shared__ bool is_last;
    if (tid == 0) {
        __threadfence();
        unsigned r = atomicInc(&g_done, gridDim.x - 1);  // wraps to 0 on last
        is_last = (r == gridDim.x - 1);
    }
    __syncthreads();

    if (is_last && tid < 32) {
        __threadfence();
        float contrib = 0.0f;
        float nb = 0.0f;
        if (tid < NBINS) {
            float cb = __ldcg(&g_cnts[tid]);
            float sb = __ldcg(&g_sums[tid]);
            contrib = sb / fmaxf(cb, 1.0f);   // empty bin: sb==0 -> 0
            nb = (cb > 0.0f) ? 1.0f : 0.0f;
            g_cnts[tid] = 0.0f;               // reset for next graph replay
            g_sums[tid] = 0.0f;
        }
#pragma unroll
        for (int o = 16; o > 0; o >>= 1) {
            contrib += __shfl_down_sync(0xffffffffu, contrib, o);
            nb      += __shfl_down_sync(0xffffffffu, nb, o);
        }
        if (tid == 0)
            out[0] = contrib / fmaxf(nb, 1.0f);   // LOSS_WEIGHT = 1.0
    }
}

extern "C" void kernel_launch(void* const* d_in, const int* in_sizes, int n_in,
                              void* d_out, int out_size) {
    const float4* pred4 = (const float4*)d_in[0];
    const int4*   targ4 = (const int4*)d_in[1];
    const float4* lw4   = (const float4*)d_in[2];
    float* out = (float*)d_out;

    int n  = in_sizes[0];
    int n4 = n >> 2;   // 67,108,864 / 4 = 16,777,216

    // 148 SMs x 8 resident blocks (20KB smem, <=32 regs) -> one full wave.
    ghmc_fused<<<1184, TPB>>>(pred4, targ4, lw4, n4, out);
}